// round 1
// baseline (speedup 1.0000x reference)
#include <cuda_runtime.h>

#define B_  4
#define N_  8192
#define C_  64
#define M_  2048
#define NW_ 7
#define BM  128
#define BN  128
#define NQB (M_/BM)     // 16
#define SCALE 0.125f    // 1/sqrt(64)

// ---------------- scratch (static device arrays; no allocation) ----------------
__device__ float g_Q[B_*N_*C_];          // 8 MB
__device__ float g_K[B_*N_*C_];          // 8 MB
__device__ float g_V[B_*N_*C_];          // 8 MB
__device__ float g_O[(long)B_*NW_*M_*C_]; // 14.7 MB  per-window normalized outputs
__device__ float g_D[B_*NW_*M_];         // softmax denominators exp(lse)

// =============================================================================
// Kernel 1: QKV projection.  rows = b*n = 32768, each CTA does 64 rows.
// dyn smem: xT[64][64] (x transposed) + Ws[64][192] (Wq|Wk|Wv row-major by c_in)
// =============================================================================
__global__ __launch_bounds__(256) void qkv_kernel(const float* __restrict__ x,
                                                  const float* __restrict__ Wq,
                                                  const float* __restrict__ Wk,
                                                  const float* __restrict__ Wv) {
    extern __shared__ float sm1[];
    float* xT = sm1;            // [c][row]  64*64
    float* Ws = sm1 + 4096;     // [c][m*64+j] 64*192
    const int tid = threadIdx.x;
    const long rowbase = (long)blockIdx.x * 64;

    // load x transposed: lane-per-row -> conflict-free scalar STS
    #pragma unroll
    for (int k = 0; k < 4; k++) {
        int l = tid + k*256;
        int row = l & 63, cg = l >> 6;           // cg 0..15
        float4 v = *(const float4*)(x + (rowbase + row)*C_ + cg*4);
        xT[(cg*4+0)*64 + row] = v.x;
        xT[(cg*4+1)*64 + row] = v.y;
        xT[(cg*4+2)*64 + row] = v.z;
        xT[(cg*4+3)*64 + row] = v.w;
    }
    // load weights (row-major, contiguous)
    {
        const float* Wm[3] = {Wq, Wk, Wv};
        #pragma unroll
        for (int m = 0; m < 3; m++)
            #pragma unroll
            for (int k = 0; k < 4; k++) {
                int l = tid + k*256;
                int cc = l >> 4, jg = l & 15;
                *(float4*)&Ws[cc*192 + m*64 + jg*4] = *(const float4*)(Wm[m] + cc*64 + jg*4);
            }
    }
    __syncthreads();

    const int ty = tid >> 4, tx = tid & 15;      // rows ty*4.., cols tx*4 per matrix
    float acc[3][4][4];
    #pragma unroll
    for (int m = 0; m < 3; m++)
        #pragma unroll
        for (int i = 0; i < 4; i++)
            #pragma unroll
            for (int j = 0; j < 4; j++) acc[m][i][j] = 0.f;

    const float* xp = xT + ty*4;
    #pragma unroll 4
    for (int cc = 0; cc < 64; cc++) {
        float4 xv = *(const float4*)(xp + cc*64);
        float4 w0 = *(const float4*)(Ws + cc*192 +   0 + tx*4);
        float4 w1 = *(const float4*)(Ws + cc*192 +  64 + tx*4);
        float4 w2 = *(const float4*)(Ws + cc*192 + 128 + tx*4);
        float xs[4] = {xv.x, xv.y, xv.z, xv.w};
        float wq[4] = {w0.x, w0.y, w0.z, w0.w};
        float wk[4] = {w1.x, w1.y, w1.z, w1.w};
        float wv[4] = {w2.x, w2.y, w2.z, w2.w};
        #pragma unroll
        for (int i = 0; i < 4; i++)
            #pragma unroll
            for (int j = 0; j < 4; j++) {
                acc[0][i][j] += xs[i]*wq[j];
                acc[1][i][j] += xs[i]*wk[j];
                acc[2][i][j] += xs[i]*wv[j];
            }
    }
    #pragma unroll
    for (int i = 0; i < 4; i++) {
        long r = (rowbase + ty*4 + i)*C_ + tx*4;
        *(float4*)&g_Q[r] = make_float4(acc[0][i][0]*SCALE, acc[0][i][1]*SCALE,
                                        acc[0][i][2]*SCALE, acc[0][i][3]*SCALE);
        *(float4*)&g_K[r] = make_float4(acc[1][i][0], acc[1][i][1], acc[1][i][2], acc[1][i][3]);
        *(float4*)&g_V[r] = make_float4(acc[2][i][0], acc[2][i][1], acc[2][i][2], acc[2][i][3]);
    }
}

// =============================================================================
// Kernel 2: causal flash attention per (b, window, q-block of 128 rows).
// grid.x = 16*28 = 448, heavy q-blocks first. dyn smem 160KB:
//   QT[64][128], KT[64][128] (c-major), Vs[128][64], PT[128][128] (k-major P)
// =============================================================================
__global__ __launch_bounds__(256, 1) void attn_kernel() {
    extern __shared__ float sm[];
    float* QT = sm;
    float* KT = sm + 8192;
    float* Vs = sm + 16384;
    float* PT = sm + 24576;

    const int tid = threadIdx.x;
    const int blk = blockIdx.x;
    const int qb  = (NQB - 1) - (blk / (B_*NW_));   // heaviest first
    const int w   = blk % (B_*NW_);
    const int b   = w / NW_;
    const int wi  = w % NW_;

    int base, r;
    if      (wi < 4) { base = wi*2048;      r = 1; }
    else if (wi < 6) { base = (wi-4)*4096;  r = 2; }
    else             { base = 0;            r = 4; }

    const float* Qg = g_Q + ((long)b*N_ + base)*C_;
    const float* Kg = g_K + ((long)b*N_ + base)*C_;
    const float* Vg = g_V + ((long)b*N_ + base)*C_;
    const int rstride = r * C_;

    // fill QT (transposed): lane-per-row -> conflict-free STS
    #pragma unroll
    for (int k = 0; k < 8; k++) {
        int l = tid + k*256;
        int row = l & 127, cg = l >> 7;
        float4 v = *(const float4*)(Qg + (long)(qb*BM + row)*rstride + cg*4);
        QT[(cg*4+0)*128 + row] = v.x;
        QT[(cg*4+1)*128 + row] = v.y;
        QT[(cg*4+2)*128 + row] = v.z;
        QT[(cg*4+3)*128 + row] = v.w;
    }

    const int ty = tid >> 4, tx = tid & 15;   // S tile: rows ty*8.., cols tx*8..; O cols tx*4..
    float mrow[8], lsum[8], Oa[8][4];
    #pragma unroll
    for (int i = 0; i < 8; i++) {
        mrow[i] = -1e30f; lsum[i] = 0.f;
        #pragma unroll
        for (int c = 0; c < 4; c++) Oa[i][c] = 0.f;
    }

    for (int kb = 0; kb <= qb; kb++) {
        __syncthreads();   // previous iteration's consumers done (also orders QT fill)

        // fill KT (transposed) + Vs (row-major)
        #pragma unroll
        for (int k = 0; k < 8; k++) {
            int l = tid + k*256;
            int row = l & 127, cg = l >> 7;
            float4 v = *(const float4*)(Kg + (long)(kb*BN + row)*rstride + cg*4);
            KT[(cg*4+0)*128 + row] = v.x;
            KT[(cg*4+1)*128 + row] = v.y;
            KT[(cg*4+2)*128 + row] = v.z;
            KT[(cg*4+3)*128 + row] = v.w;
        }
        #pragma unroll
        for (int k = 0; k < 8; k++) {
            int l = tid + k*256;
            int cg = l & 15, row = l >> 4;
            *(float4*)&Vs[row*64 + cg*4] =
                *(const float4*)(Vg + (long)(kb*BN + row)*rstride + cg*4);
        }
        __syncthreads();

        // ---- S = Q K^T (128x128, 8x8 per thread) ----
        float s[8][8];
        #pragma unroll
        for (int i = 0; i < 8; i++)
            #pragma unroll
            for (int j = 0; j < 8; j++) s[i][j] = 0.f;

        const float* qptr = QT + (ty << 3);
        const float* kptr = KT + (tx << 3);
        #pragma unroll 2
        for (int cc = 0; cc < 64; cc++) {
            float4 q0 = *(const float4*)(qptr + cc*128);
            float4 q1 = *(const float4*)(qptr + cc*128 + 4);
            float4 k0 = *(const float4*)(kptr + cc*128);
            float4 k1 = *(const float4*)(kptr + cc*128 + 4);
            float qv[8] = {q0.x,q0.y,q0.z,q0.w,q1.x,q1.y,q1.z,q1.w};
            float kv[8] = {k0.x,k0.y,k0.z,k0.w,k1.x,k1.y,k1.z,k1.w};
            #pragma unroll
            for (int i = 0; i < 8; i++)
                #pragma unroll
                for (int j = 0; j < 8; j++) s[i][j] += qv[i]*kv[j];
        }

        // causal mask on diagonal block
        if (kb == qb) {
            #pragma unroll
            for (int i = 0; i < 8; i++)
                #pragma unroll
                for (int j = 0; j < 8; j++)
                    if (tx*8 + j > ty*8 + i) s[i][j] = -1e30f;
        }

        // ---- online softmax (row stats shared across the 16 tx threads) ----
        #pragma unroll
        for (int i = 0; i < 8; i++) {
            float rm = s[i][0];
            #pragma unroll
            for (int j = 1; j < 8; j++) rm = fmaxf(rm, s[i][j]);
            #pragma unroll
            for (int o = 1; o < 16; o <<= 1)
                rm = fmaxf(rm, __shfl_xor_sync(0xffffffffu, rm, o));
            float mn   = fmaxf(mrow[i], rm);
            float corr = __expf(mrow[i] - mn);
            float rs = 0.f;
            #pragma unroll
            for (int j = 0; j < 8; j++) {
                float p = __expf(s[i][j] - mn);
                s[i][j] = p;
                rs += p;
            }
            #pragma unroll
            for (int o = 1; o < 16; o <<= 1)
                rs += __shfl_xor_sync(0xffffffffu, rs, o);
            lsum[i] = lsum[i]*corr + rs;
            mrow[i] = mn;
            #pragma unroll
            for (int c = 0; c < 4; c++) Oa[i][c] *= corr;
        }

        // write P transposed: PT[k][q]  (reads in PV are warp-uniform-row)
        #pragma unroll
        for (int j = 0; j < 8; j++) {
            *(float4*)&PT[(tx*8+j)*128 + ty*8    ] = make_float4(s[0][j], s[1][j], s[2][j], s[3][j]);
            *(float4*)&PT[(tx*8+j)*128 + ty*8 + 4] = make_float4(s[4][j], s[5][j], s[6][j], s[7][j]);
        }
        __syncthreads();

        // ---- O += P V  (128x64, 8x4 per thread) ----
        const float* pptr = PT + (ty << 3);
        const float* vptr = Vs + (tx << 2);
        #pragma unroll 4
        for (int kk = 0; kk < 128; kk++) {
            float4 p0 = *(const float4*)(pptr + kk*128);
            float4 p1 = *(const float4*)(pptr + kk*128 + 4);
            float4 vv = *(const float4*)(vptr + kk*64);
            float pv[8] = {p0.x,p0.y,p0.z,p0.w,p1.x,p1.y,p1.z,p1.w};
            float vs4[4] = {vv.x,vv.y,vv.z,vv.w};
            #pragma unroll
            for (int i = 0; i < 8; i++)
                #pragma unroll
                for (int c = 0; c < 4; c++) Oa[i][c] += pv[i]*vs4[c];
        }
    }

    // epilogue: normalized o + denom = l * exp(m)  (= exp(lse))
    float* Og = g_O + ((long)(b*NW_ + wi)*M_ + qb*BM)*C_;
    float* Dg = g_D + (long)(b*NW_ + wi)*M_ + qb*BM;
    #pragma unroll
    for (int i = 0; i < 8; i++) {
        float inv = 1.0f / lsum[i];
        *(float4*)(Og + (ty*8+i)*C_ + tx*4) =
            make_float4(Oa[i][0]*inv, Oa[i][1]*inv, Oa[i][2]*inv, Oa[i][3]*inv);
        if (tx == 0) Dg[ty*8+i] = lsum[i] * __expf(mrow[i]);
    }
}

// =============================================================================
// Kernel 3: mix — out[b,p,:] = sum_w d_w * o_w / sum_w d_w. 4 positions per CTA.
// =============================================================================
__global__ __launch_bounds__(256) void mix_kernel(float* __restrict__ out) {
    const int tid = threadIdx.x;
    const int c = tid & 63;
    const int gp = blockIdx.x*4 + (tid >> 6);
    const int b = gp >> 13;
    const int p = gp & (N_-1);

    int w0 = p >> 11, r0 = p & 2047;
    long i0 = (long)(b*NW_ + w0)*M_ + r0;
    float d0 = g_D[i0];
    float dsum = d0;
    float num  = d0 * g_O[i0*C_ + c];

    if ((p & 1) == 0) {
        int w1 = 4 + (p >> 12), r1 = (p & 4095) >> 1;
        long i1 = (long)(b*NW_ + w1)*M_ + r1;
        float d1 = g_D[i1];
        dsum += d1;
        num  += d1 * g_O[i1*C_ + c];
    }
    if ((p & 3) == 0) {
        long i2 = (long)(b*NW_ + 6)*M_ + (p >> 2);
        float d2 = g_D[i2];
        dsum += d2;
        num  += d2 * g_O[i2*C_ + c];
    }
    out[((long)b*N_ + p)*C_ + c] = num / dsum;
}

// =============================================================================
extern "C" void kernel_launch(void* const* d_in, const int* in_sizes, int n_in,
                              void* d_out, int out_size) {
    (void)in_sizes; (void)n_in; (void)out_size;
    const float* x  = (const float*)d_in[0];
    const float* Wq = (const float*)d_in[1];
    const float* Wk = (const float*)d_in[2];
    const float* Wv = (const float*)d_in[3];
    float* out = (float*)d_out;

    const int smem1 = (64*64 + 64*192) * 4;                    // 64 KB
    const int smem2 = (8192 + 8192 + 8192 + 16384) * 4;        // 160 KB
    cudaFuncSetAttribute(qkv_kernel,  cudaFuncAttributeMaxDynamicSharedMemorySize, smem1);
    cudaFuncSetAttribute(attn_kernel, cudaFuncAttributeMaxDynamicSharedMemorySize, smem2);

    qkv_kernel<<<(B_*N_)/64, 256, smem1>>>(x, Wq, Wk, Wv);
    attn_kernel<<<NQB * B_ * NW_, 256, smem2>>>();
    mix_kernel<<<(B_*N_)/4, 256>>>(out);
}

// round 2
// speedup vs baseline: 1.0014x; 1.0014x over previous
#include <cuda_runtime.h>

#define B_  4
#define N_  8192
#define C_  64
#define M_  2048
#define NW_ 7
#define BM  128
#define BN  128
#define NQB (M_/BM)     // 16
#define SCALE 0.125f    // 1/sqrt(64)

// ---------------- scratch (static device arrays; no allocation) ----------------
__device__ float g_Q[B_*N_*C_];          // 8 MB
__device__ float g_K[B_*N_*C_];          // 8 MB
__device__ float g_V[B_*N_*C_];          // 8 MB
__device__ float g_O[(long)B_*NW_*M_*C_]; // 14.7 MB  per-window normalized outputs
__device__ float g_D[B_*NW_*M_];         // softmax denominators exp(lse)

// =============================================================================
// Kernel 1: QKV projection.  rows = b*n = 32768, each CTA does 64 rows.
// dyn smem: xT[64][64] (x transposed) + Ws[64][192] (Wq|Wk|Wv row-major by c_in)
// =============================================================================
__global__ __launch_bounds__(256) void qkv_kernel(const float* __restrict__ x,
                                                  const float* __restrict__ Wq,
                                                  const float* __restrict__ Wk,
                                                  const float* __restrict__ Wv) {
    extern __shared__ float sm1[];
    float* xT = sm1;            // [c][row]  64*64
    float* Ws = sm1 + 4096;     // [c][m*64+j] 64*192
    const int tid = threadIdx.x;
    const long rowbase = (long)blockIdx.x * 64;

    // load x transposed: lane-per-row -> conflict-free scalar STS
    #pragma unroll
    for (int k = 0; k < 4; k++) {
        int l = tid + k*256;
        int row = l & 63, cg = l >> 6;           // cg 0..15
        float4 v = *(const float4*)(x + (rowbase + row)*C_ + cg*4);
        xT[(cg*4+0)*64 + row] = v.x;
        xT[(cg*4+1)*64 + row] = v.y;
        xT[(cg*4+2)*64 + row] = v.z;
        xT[(cg*4+3)*64 + row] = v.w;
    }
    // load weights (row-major, contiguous)
    {
        const float* Wm[3] = {Wq, Wk, Wv};
        #pragma unroll
        for (int m = 0; m < 3; m++)
            #pragma unroll
            for (int k = 0; k < 4; k++) {
                int l = tid + k*256;
                int cc = l >> 4, jg = l & 15;
                *(float4*)&Ws[cc*192 + m*64 + jg*4] = *(const float4*)(Wm[m] + cc*64 + jg*4);
            }
    }
    __syncthreads();

    const int ty = tid >> 4, tx = tid & 15;      // rows ty*4.., cols tx*4 per matrix
    float acc[3][4][4];
    #pragma unroll
    for (int m = 0; m < 3; m++)
        #pragma unroll
        for (int i = 0; i < 4; i++)
            #pragma unroll
            for (int j = 0; j < 4; j++) acc[m][i][j] = 0.f;

    const float* xp = xT + ty*4;
    #pragma unroll 4
    for (int cc = 0; cc < 64; cc++) {
        float4 xv = *(const float4*)(xp + cc*64);
        float4 w0 = *(const float4*)(Ws + cc*192 +   0 + tx*4);
        float4 w1 = *(const float4*)(Ws + cc*192 +  64 + tx*4);
        float4 w2 = *(const float4*)(Ws + cc*192 + 128 + tx*4);
        float xs[4] = {xv.x, xv.y, xv.z, xv.w};
        float wq[4] = {w0.x, w0.y, w0.z, w0.w};
        float wk[4] = {w1.x, w1.y, w1.z, w1.w};
        float wv[4] = {w2.x, w2.y, w2.z, w2.w};
        #pragma unroll
        for (int i = 0; i < 4; i++)
            #pragma unroll
            for (int j = 0; j < 4; j++) {
                acc[0][i][j] += xs[i]*wq[j];
                acc[1][i][j] += xs[i]*wk[j];
                acc[2][i][j] += xs[i]*wv[j];
            }
    }
    #pragma unroll
    for (int i = 0; i < 4; i++) {
        long r = (rowbase + ty*4 + i)*C_ + tx*4;
        *(float4*)&g_Q[r] = make_float4(acc[0][i][0]*SCALE, acc[0][i][1]*SCALE,
                                        acc[0][i][2]*SCALE, acc[0][i][3]*SCALE);
        *(float4*)&g_K[r] = make_float4(acc[1][i][0], acc[1][i][1], acc[1][i][2], acc[1][i][3]);
        *(float4*)&g_V[r] = make_float4(acc[2][i][0], acc[2][i][1], acc[2][i][2], acc[2][i][3]);
    }
}

// =============================================================================
// Kernel 2: causal flash attention per (b, window, q-block of 128 rows).
// grid.x = 16*28 = 448, heavy q-blocks first. dyn smem 160KB:
//   QT[64][128], KT[64][128] (c-major), Vs[128][64], PT[128][128] (k-major P)
// =============================================================================
__global__ __launch_bounds__(256, 1) void attn_kernel() {
    extern __shared__ float sm[];
    float* QT = sm;
    float* KT = sm + 8192;
    float* Vs = sm + 16384;
    float* PT = sm + 24576;

    const int tid = threadIdx.x;
    const int blk = blockIdx.x;
    const int qb  = (NQB - 1) - (blk / (B_*NW_));   // heaviest first
    const int w   = blk % (B_*NW_);
    const int b   = w / NW_;
    const int wi  = w % NW_;

    int base, r;
    if      (wi < 4) { base = wi*2048;      r = 1; }
    else if (wi < 6) { base = (wi-4)*4096;  r = 2; }
    else             { base = 0;            r = 4; }

    const float* Qg = g_Q + ((long)b*N_ + base)*C_;
    const float* Kg = g_K + ((long)b*N_ + base)*C_;
    const float* Vg = g_V + ((long)b*N_ + base)*C_;
    const int rstride = r * C_;

    // fill QT (transposed): lane-per-row -> conflict-free STS
    #pragma unroll
    for (int k = 0; k < 8; k++) {
        int l = tid + k*256;
        int row = l & 127, cg = l >> 7;
        float4 v = *(const float4*)(Qg + (long)(qb*BM + row)*rstride + cg*4);
        QT[(cg*4+0)*128 + row] = v.x;
        QT[(cg*4+1)*128 + row] = v.y;
        QT[(cg*4+2)*128 + row] = v.z;
        QT[(cg*4+3)*128 + row] = v.w;
    }

    const int ty = tid >> 4, tx = tid & 15;   // S tile: rows ty*8.., cols tx*8..; O cols tx*4..
    float mrow[8], lsum[8], Oa[8][4];
    #pragma unroll
    for (int i = 0; i < 8; i++) {
        mrow[i] = -1e30f; lsum[i] = 0.f;
        #pragma unroll
        for (int c = 0; c < 4; c++) Oa[i][c] = 0.f;
    }

    for (int kb = 0; kb <= qb; kb++) {
        __syncthreads();   // previous iteration's consumers done (also orders QT fill)

        // fill KT (transposed) + Vs (row-major)
        #pragma unroll
        for (int k = 0; k < 8; k++) {
            int l = tid + k*256;
            int row = l & 127, cg = l >> 7;
            float4 v = *(const float4*)(Kg + (long)(kb*BN + row)*rstride + cg*4);
            KT[(cg*4+0)*128 + row] = v.x;
            KT[(cg*4+1)*128 + row] = v.y;
            KT[(cg*4+2)*128 + row] = v.z;
            KT[(cg*4+3)*128 + row] = v.w;
        }
        #pragma unroll
        for (int k = 0; k < 8; k++) {
            int l = tid + k*256;
            int cg = l & 15, row = l >> 4;
            *(float4*)&Vs[row*64 + cg*4] =
                *(const float4*)(Vg + (long)(kb*BN + row)*rstride + cg*4);
        }
        __syncthreads();

        // ---- S = Q K^T (128x128, 8x8 per thread) ----
        float s[8][8];
        #pragma unroll
        for (int i = 0; i < 8; i++)
            #pragma unroll
            for (int j = 0; j < 8; j++) s[i][j] = 0.f;

        const float* qptr = QT + (ty << 3);
        const float* kptr = KT + (tx << 3);
        #pragma unroll 2
        for (int cc = 0; cc < 64; cc++) {
            float4 q0 = *(const float4*)(qptr + cc*128);
            float4 q1 = *(const float4*)(qptr + cc*128 + 4);
            float4 k0 = *(const float4*)(kptr + cc*128);
            float4 k1 = *(const float4*)(kptr + cc*128 + 4);
            float qv[8] = {q0.x,q0.y,q0.z,q0.w,q1.x,q1.y,q1.z,q1.w};
            float kv[8] = {k0.x,k0.y,k0.z,k0.w,k1.x,k1.y,k1.z,k1.w};
            #pragma unroll
            for (int i = 0; i < 8; i++)
                #pragma unroll
                for (int j = 0; j < 8; j++) s[i][j] += qv[i]*kv[j];
        }

        // causal mask on diagonal block
        if (kb == qb) {
            #pragma unroll
            for (int i = 0; i < 8; i++)
                #pragma unroll
                for (int j = 0; j < 8; j++)
                    if (tx*8 + j > ty*8 + i) s[i][j] = -1e30f;
        }

        // ---- online softmax (row stats shared across the 16 tx threads) ----
        #pragma unroll
        for (int i = 0; i < 8; i++) {
            float rm = s[i][0];
            #pragma unroll
            for (int j = 1; j < 8; j++) rm = fmaxf(rm, s[i][j]);
            #pragma unroll
            for (int o = 1; o < 16; o <<= 1)
                rm = fmaxf(rm, __shfl_xor_sync(0xffffffffu, rm, o));
            float mn   = fmaxf(mrow[i], rm);
            float corr = __expf(mrow[i] - mn);
            float rs = 0.f;
            #pragma unroll
            for (int j = 0; j < 8; j++) {
                float p = __expf(s[i][j] - mn);
                s[i][j] = p;
                rs += p;
            }
            #pragma unroll
            for (int o = 1; o < 16; o <<= 1)
                rs += __shfl_xor_sync(0xffffffffu, rs, o);
            lsum[i] = lsum[i]*corr + rs;
            mrow[i] = mn;
            #pragma unroll
            for (int c = 0; c < 4; c++) Oa[i][c] *= corr;
        }

        // write P transposed: PT[k][q]  (reads in PV are warp-uniform-row)
        #pragma unroll
        for (int j = 0; j < 8; j++) {
            *(float4*)&PT[(tx*8+j)*128 + ty*8    ] = make_float4(s[0][j], s[1][j], s[2][j], s[3][j]);
            *(float4*)&PT[(tx*8+j)*128 + ty*8 + 4] = make_float4(s[4][j], s[5][j], s[6][j], s[7][j]);
        }
        __syncthreads();

        // ---- O += P V  (128x64, 8x4 per thread) ----
        const float* pptr = PT + (ty << 3);
        const float* vptr = Vs + (tx << 2);
        #pragma unroll 4
        for (int kk = 0; kk < 128; kk++) {
            float4 p0 = *(const float4*)(pptr + kk*128);
            float4 p1 = *(const float4*)(pptr + kk*128 + 4);
            float4 vv = *(const float4*)(vptr + kk*64);
            float pv[8] = {p0.x,p0.y,p0.z,p0.w,p1.x,p1.y,p1.z,p1.w};
            float vs4[4] = {vv.x,vv.y,vv.z,vv.w};
            #pragma unroll
            for (int i = 0; i < 8; i++)
                #pragma unroll
                for (int c = 0; c < 4; c++) Oa[i][c] += pv[i]*vs4[c];
        }
    }

    // epilogue: normalized o + denom = l * exp(m)  (= exp(lse))
    float* Og = g_O + ((long)(b*NW_ + wi)*M_ + qb*BM)*C_;
    float* Dg = g_D + (long)(b*NW_ + wi)*M_ + qb*BM;
    #pragma unroll
    for (int i = 0; i < 8; i++) {
        float inv = 1.0f / lsum[i];
        *(float4*)(Og + (ty*8+i)*C_ + tx*4) =
            make_float4(Oa[i][0]*inv, Oa[i][1]*inv, Oa[i][2]*inv, Oa[i][3]*inv);
        if (tx == 0) Dg[ty*8+i] = lsum[i] * __expf(mrow[i]);
    }
}

// =============================================================================
// Kernel 3: mix — out[b,p,:] = sum_w d_w * o_w / sum_w d_w. 4 positions per CTA.
// =============================================================================
__global__ __launch_bounds__(256) void mix_kernel(float* __restrict__ out) {
    const int tid = threadIdx.x;
    const int c = tid & 63;
    const int gp = blockIdx.x*4 + (tid >> 6);
    const int b = gp >> 13;
    const int p = gp & (N_-1);

    int w0 = p >> 11, r0 = p & 2047;
    long i0 = (long)(b*NW_ + w0)*M_ + r0;
    float d0 = g_D[i0];
    float dsum = d0;
    float num  = d0 * g_O[i0*C_ + c];

    if ((p & 1) == 0) {
        int w1 = 4 + (p >> 12), r1 = (p & 4095) >> 1;
        long i1 = (long)(b*NW_ + w1)*M_ + r1;
        float d1 = g_D[i1];
        dsum += d1;
        num  += d1 * g_O[i1*C_ + c];
    }
    if ((p & 3) == 0) {
        long i2 = (long)(b*NW_ + 6)*M_ + (p >> 2);
        float d2 = g_D[i2];
        dsum += d2;
        num  += d2 * g_O[i2*C_ + c];
    }
    out[((long)b*N_ + p)*C_ + c] = num / dsum;
}

// =============================================================================
extern "C" void kernel_launch(void* const* d_in, const int* in_sizes, int n_in,
                              void* d_out, int out_size) {
    (void)in_sizes; (void)n_in; (void)out_size;
    const float* x  = (const float*)d_in[0];
    const float* Wq = (const float*)d_in[1];
    const float* Wk = (const float*)d_in[2];
    const float* Wv = (const float*)d_in[3];
    float* out = (float*)d_out;

    const int smem1 = (64*64 + 64*192) * 4;                    // 64 KB
    const int smem2 = (8192 + 8192 + 8192 + 16384) * 4;        // 160 KB
    cudaFuncSetAttribute(qkv_kernel,  cudaFuncAttributeMaxDynamicSharedMemorySize, smem1);
    cudaFuncSetAttribute(attn_kernel, cudaFuncAttributeMaxDynamicSharedMemorySize, smem2);

    qkv_kernel<<<(B_*N_)/64, 256, smem1>>>(x, Wq, Wk, Wv);
    attn_kernel<<<NQB * B_ * NW_, 256, smem2>>>();
    mix_kernel<<<(B_*N_)/4, 256>>>(out);
}

// round 3
// speedup vs baseline: 3.2577x; 3.2533x over previous
#include <cuda_runtime.h>

#define B_  4
#define N_  8192
#define C_  64
#define M_  2048
#define NW_ 7
#define QB_ROWS 256
#define NQB 8
#define KSTEP 64
#define KST 68
#define VST 72
#define SCALE_LOG2 0.18033688011112042f  // (1/8) * log2(e)

__device__ float g_Q[B_*N_*C_];
__device__ float g_K[B_*N_*C_];
__device__ float g_V[B_*N_*C_];
__device__ float g_O[(long)B_*NW_*M_*C_];
__device__ float g_D[B_*NW_*M_];

__device__ __forceinline__ unsigned tf32u(float x) {
    unsigned u; asm("cvt.rna.tf32.f32 %0, %1;" : "=r"(u) : "f"(x)); return u;
}
__device__ __forceinline__ float ex2(float x) {
    float y; asm("ex2.approx.f32 %0, %1;" : "=f"(y) : "f"(x)); return y;
}
__device__ __forceinline__ void mma8(float d[4], const unsigned a[4], unsigned b0, unsigned b1) {
    asm volatile("mma.sync.aligned.m16n8k8.row.col.f32.tf32.tf32.f32 "
        "{%0,%1,%2,%3},{%4,%5,%6,%7},{%8,%9},{%0,%1,%2,%3};"
        : "+f"(d[0]), "+f"(d[1]), "+f"(d[2]), "+f"(d[3])
        : "r"(a[0]), "r"(a[1]), "r"(a[2]), "r"(a[3]), "r"(b0), "r"(b1));
}

// ============================ Kernel 1: QKV ============================
__global__ __launch_bounds__(256) void qkv_kernel(const float* __restrict__ x,
                                                  const float* __restrict__ Wq,
                                                  const float* __restrict__ Wk,
                                                  const float* __restrict__ Wv) {
    extern __shared__ float sm1[];
    float* xT = sm1;
    float* Ws = sm1 + 4096;
    const int tid = threadIdx.x;
    const long rowbase = (long)blockIdx.x * 64;

    #pragma unroll
    for (int k = 0; k < 4; k++) {
        int l = tid + k*256;
        int row = l & 63, cg = l >> 6;
        float4 v = *(const float4*)(x + (rowbase + row)*C_ + cg*4);
        xT[(cg*4+0)*64 + row] = v.x;
        xT[(cg*4+1)*64 + row] = v.y;
        xT[(cg*4+2)*64 + row] = v.z;
        xT[(cg*4+3)*64 + row] = v.w;
    }
    {
        const float* Wm[3] = {Wq, Wk, Wv};
        #pragma unroll
        for (int m = 0; m < 3; m++)
            #pragma unroll
            for (int k = 0; k < 4; k++) {
                int l = tid + k*256;
                int cc = l >> 4, jg = l & 15;
                *(float4*)&Ws[cc*192 + m*64 + jg*4] = *(const float4*)(Wm[m] + cc*64 + jg*4);
            }
    }
    __syncthreads();

    const int ty = tid >> 4, tx = tid & 15;
    float acc[3][4][4];
    #pragma unroll
    for (int m = 0; m < 3; m++)
        #pragma unroll
        for (int i = 0; i < 4; i++)
            #pragma unroll
            for (int j = 0; j < 4; j++) acc[m][i][j] = 0.f;

    const float* xp = xT + ty*4;
    #pragma unroll 4
    for (int cc = 0; cc < 64; cc++) {
        float4 xv = *(const float4*)(xp + cc*64);
        float4 w0 = *(const float4*)(Ws + cc*192 +   0 + tx*4);
        float4 w1 = *(const float4*)(Ws + cc*192 +  64 + tx*4);
        float4 w2 = *(const float4*)(Ws + cc*192 + 128 + tx*4);
        float xs[4] = {xv.x, xv.y, xv.z, xv.w};
        float wq[4] = {w0.x, w0.y, w0.z, w0.w};
        float wk[4] = {w1.x, w1.y, w1.z, w1.w};
        float wv[4] = {w2.x, w2.y, w2.z, w2.w};
        #pragma unroll
        for (int i = 0; i < 4; i++)
            #pragma unroll
            for (int j = 0; j < 4; j++) {
                acc[0][i][j] += xs[i]*wq[j];
                acc[1][i][j] += xs[i]*wk[j];
                acc[2][i][j] += xs[i]*wv[j];
            }
    }
    #pragma unroll
    for (int i = 0; i < 4; i++) {
        long rr = (rowbase + ty*4 + i)*C_ + tx*4;
        *(float4*)&g_Q[rr] = make_float4(acc[0][i][0]*SCALE_LOG2, acc[0][i][1]*SCALE_LOG2,
                                         acc[0][i][2]*SCALE_LOG2, acc[0][i][3]*SCALE_LOG2);
        *(float4*)&g_K[rr] = make_float4(acc[1][i][0], acc[1][i][1], acc[1][i][2], acc[1][i][3]);
        *(float4*)&g_V[rr] = make_float4(acc[2][i][0], acc[2][i][1], acc[2][i][2], acc[2][i][3]);
    }
}

// ==================== Kernel 2: tf32 flash attention ====================
__global__ __launch_bounds__(256, 1) void attn_kernel() {
    extern __shared__ unsigned smu[];
    unsigned* Ks = smu;              // [64][KST]
    unsigned* Vs = smu + 64*KST;     // [64][VST]

    const int tid  = threadIdx.x;
    const int wid  = tid >> 5, lane = tid & 31;
    const int g    = lane >> 2, t4 = lane & 3;
    const int blk  = blockIdx.x;
    const int qb   = (NQB - 1) - blk / (B_*NW_);
    const int w    = blk % (B_*NW_);
    const int b    = w / NW_, wi = w % NW_;

    int base, r;
    if      (wi < 4) { base = wi*2048;     r = 1; }
    else if (wi < 6) { base = (wi-4)*4096; r = 2; }
    else             { base = 0;           r = 4; }

    const float* Qg = g_Q + ((long)b*N_ + base)*C_;
    const float* Kg = g_K + ((long)b*N_ + base)*C_;
    const float* Vg = g_V + ((long)b*N_ + base)*C_;
    const int rs = r * C_;

    const int row0 = qb*QB_ROWS + 32*wid;
    unsigned qa[2][8][4];
    #pragma unroll
    for (int mt = 0; mt < 2; mt++) {
        const float* q0 = Qg + (long)(row0 + 16*mt + g)*rs;
        const float* q1 = q0 + (long)8*rs;
        #pragma unroll
        for (int s = 0; s < 8; s++) {
            qa[mt][s][0] = tf32u(q0[8*s + t4]);
            qa[mt][s][1] = tf32u(q1[8*s + t4]);
            qa[mt][s][2] = tf32u(q0[8*s + t4 + 4]);
            qa[mt][s][3] = tf32u(q1[8*s + t4 + 4]);
        }
    }

    float oacc[2][8][4];
    float mrow[2][2], lrow[2][2];
    #pragma unroll
    for (int mt = 0; mt < 2; mt++) {
        mrow[mt][0] = mrow[mt][1] = -1e30f;
        lrow[mt][0] = lrow[mt][1] = 0.f;
        #pragma unroll
        for (int j = 0; j < 8; j++)
            #pragma unroll
            for (int q = 0; q < 4; q++) oacc[mt][j][q] = 0.f;
    }

    const int nks = 4*qb + 4;
    for (int ks = 0; ks < nks; ks++) {
        __syncthreads();
        // fill K (rows permuted by kappa within groups of 8) and V, cvt tf32
        #pragma unroll
        for (int i = 0; i < 4; i++) {
            int l = tid + i*256;
            int slot = l >> 4, cg = l & 15;
            int srck = (slot & ~7) | ((slot & 1) << 2) | ((slot & 7) >> 1);
            float4 kv = *(const float4*)(Kg + (long)(ks*KSTEP + srck)*rs + cg*4);
            uint4 ku; ku.x = tf32u(kv.x); ku.y = tf32u(kv.y); ku.z = tf32u(kv.z); ku.w = tf32u(kv.w);
            *(uint4*)&Ks[slot*KST + cg*4] = ku;
            float4 vv = *(const float4*)(Vg + (long)(ks*KSTEP + slot)*rs + cg*4);
            uint4 vu; vu.x = tf32u(vv.x); vu.y = tf32u(vv.y); vu.z = tf32u(vv.z); vu.w = tf32u(vv.w);
            *(uint4*)&Vs[slot*VST + cg*4] = vu;
        }
        __syncthreads();

        // ---- S = Q K^T ----
        float sacc[2][8][4];
        #pragma unroll
        for (int mt = 0; mt < 2; mt++)
            #pragma unroll
            for (int j = 0; j < 8; j++)
                #pragma unroll
                for (int q = 0; q < 4; q++) sacc[mt][j][q] = 0.f;

        #pragma unroll
        for (int s = 0; s < 8; s++) {
            #pragma unroll
            for (int j = 0; j < 8; j++) {
                unsigned b0 = Ks[(8*j + g)*KST + 8*s + t4];
                unsigned b1 = Ks[(8*j + g)*KST + 8*s + t4 + 4];
                mma8(sacc[0][j], qa[0][s], b0, b1);
                mma8(sacc[1][j], qa[1][s], b0, b1);
            }
        }

        // ---- causal mask (logical keys: c0->8j+t4, c1->8j+t4+4) ----
        if (ks >= 4*qb) {
            #pragma unroll
            for (int mt = 0; mt < 2; mt++) {
                int r0_ = row0 + 16*mt + g, r1_ = r0_ + 8;
                #pragma unroll
                for (int j = 0; j < 8; j++) {
                    int k0 = ks*KSTEP + 8*j + t4, k1 = k0 + 4;
                    if (k0 > r0_) sacc[mt][j][0] = -1e30f;
                    if (k1 > r0_) sacc[mt][j][1] = -1e30f;
                    if (k0 > r1_) sacc[mt][j][2] = -1e30f;
                    if (k1 > r1_) sacc[mt][j][3] = -1e30f;
                }
            }
        }

        // ---- online softmax in log2 domain ----
        #pragma unroll
        for (int mt = 0; mt < 2; mt++) {
            float rm0 = -1e30f, rm1 = -1e30f;
            #pragma unroll
            for (int j = 0; j < 8; j++) {
                rm0 = fmaxf(rm0, fmaxf(sacc[mt][j][0], sacc[mt][j][1]));
                rm1 = fmaxf(rm1, fmaxf(sacc[mt][j][2], sacc[mt][j][3]));
            }
            rm0 = fmaxf(rm0, __shfl_xor_sync(0xffffffffu, rm0, 1));
            rm0 = fmaxf(rm0, __shfl_xor_sync(0xffffffffu, rm0, 2));
            rm1 = fmaxf(rm1, __shfl_xor_sync(0xffffffffu, rm1, 1));
            rm1 = fmaxf(rm1, __shfl_xor_sync(0xffffffffu, rm1, 2));
            float mn0 = fmaxf(mrow[mt][0], rm0), mn1 = fmaxf(mrow[mt][1], rm1);
            float c0 = ex2(mrow[mt][0] - mn0),   c1 = ex2(mrow[mt][1] - mn1);
            mrow[mt][0] = mn0; mrow[mt][1] = mn1;
            float rs0 = 0.f, rs1 = 0.f;
            #pragma unroll
            for (int j = 0; j < 8; j++) {
                float p0 = ex2(sacc[mt][j][0] - mn0); rs0 += p0; sacc[mt][j][0] = p0;
                float p1 = ex2(sacc[mt][j][1] - mn0); rs0 += p1; sacc[mt][j][1] = p1;
                float p2 = ex2(sacc[mt][j][2] - mn1); rs1 += p2; sacc[mt][j][2] = p2;
                float p3 = ex2(sacc[mt][j][3] - mn1); rs1 += p3; sacc[mt][j][3] = p3;
            }
            rs0 += __shfl_xor_sync(0xffffffffu, rs0, 1);
            rs0 += __shfl_xor_sync(0xffffffffu, rs0, 2);
            rs1 += __shfl_xor_sync(0xffffffffu, rs1, 1);
            rs1 += __shfl_xor_sync(0xffffffffu, rs1, 2);
            lrow[mt][0] = lrow[mt][0]*c0 + rs0;
            lrow[mt][1] = lrow[mt][1]*c1 + rs1;
            #pragma unroll
            for (int jv = 0; jv < 8; jv++) {
                oacc[mt][jv][0] *= c0; oacc[mt][jv][1] *= c0;
                oacc[mt][jv][2] *= c1; oacc[mt][jv][3] *= c1;
            }
        }

        // ---- O += P V (S C-frags reused as A-frags: {c0,c2,c1,c3}) ----
        #pragma unroll
        for (int s2 = 0; s2 < 8; s2++) {
            unsigned pa0[4] = { tf32u(sacc[0][s2][0]), tf32u(sacc[0][s2][2]),
                                tf32u(sacc[0][s2][1]), tf32u(sacc[0][s2][3]) };
            unsigned pa1[4] = { tf32u(sacc[1][s2][0]), tf32u(sacc[1][s2][2]),
                                tf32u(sacc[1][s2][1]), tf32u(sacc[1][s2][3]) };
            #pragma unroll
            for (int jv = 0; jv < 8; jv++) {
                unsigned b0 = Vs[(8*s2 + t4)*VST + 8*jv + g];
                unsigned b1 = Vs[(8*s2 + t4 + 4)*VST + 8*jv + g];
                mma8(oacc[0][jv], pa0, b0, b1);
                mma8(oacc[1][jv], pa1, b0, b1);
            }
        }
    }

    // ---- epilogue: normalized O + denominators d = l * 2^m ----
    float* Og = g_O + (long)(b*NW_ + wi)*M_*C_;
    float* Dg = g_D + (long)(b*NW_ + wi)*M_;
    #pragma unroll
    for (int mt = 0; mt < 2; mt++) {
        int r0_ = row0 + 16*mt + g, r1_ = r0_ + 8;
        float i0 = 1.0f / lrow[mt][0], i1 = 1.0f / lrow[mt][1];
        #pragma unroll
        for (int jv = 0; jv < 8; jv++) {
            *(float2*)&Og[(long)r0_*C_ + 8*jv + 2*t4] =
                make_float2(oacc[mt][jv][0]*i0, oacc[mt][jv][1]*i0);
            *(float2*)&Og[(long)r1_*C_ + 8*jv + 2*t4] =
                make_float2(oacc[mt][jv][2]*i1, oacc[mt][jv][3]*i1);
        }
        if (t4 == 0) {
            Dg[r0_] = lrow[mt][0] * ex2(mrow[mt][0]);
            Dg[r1_] = lrow[mt][1] * ex2(mrow[mt][1]);
        }
    }
}

// ============================ Kernel 3: mix ============================
__global__ __launch_bounds__(256) void mix_kernel(float* __restrict__ out) {
    const int tid = threadIdx.x;
    const int c = tid & 63;
    const int gp = blockIdx.x*4 + (tid >> 6);
    const int b = gp >> 13;
    const int p = gp & (N_-1);

    int w0 = p >> 11, r0 = p & 2047;
    long i0 = (long)(b*NW_ + w0)*M_ + r0;
    float d0 = g_D[i0];
    float dsum = d0;
    float num  = d0 * g_O[i0*C_ + c];

    if ((p & 1) == 0) {
        int w1 = 4 + (p >> 12), r1 = (p & 4095) >> 1;
        long i1 = (long)(b*NW_ + w1)*M_ + r1;
        float d1 = g_D[i1];
        dsum += d1;
        num  += d1 * g_O[i1*C_ + c];
    }
    if ((p & 3) == 0) {
        long i2 = (long)(b*NW_ + 6)*M_ + (p >> 2);
        float d2 = g_D[i2];
        dsum += d2;
        num  += d2 * g_O[i2*C_ + c];
    }
    out[((long)b*N_ + p)*C_ + c] = num / dsum;
}

// =======================================================================
extern "C" void kernel_launch(void* const* d_in, const int* in_sizes, int n_in,
                              void* d_out, int out_size) {
    (void)in_sizes; (void)n_in; (void)out_size;
    const float* x  = (const float*)d_in[0];
    const float* Wq = (const float*)d_in[1];
    const float* Wk = (const float*)d_in[2];
    const float* Wv = (const float*)d_in[3];
    float* out = (float*)d_out;

    const int smem1 = (64*64 + 64*192) * 4;
    const int smem2 = (64*KST + 64*VST) * 4;
    cudaFuncSetAttribute(qkv_kernel,  cudaFuncAttributeMaxDynamicSharedMemorySize, smem1);
    cudaFuncSetAttribute(attn_kernel, cudaFuncAttributeMaxDynamicSharedMemorySize, smem2);

    qkv_kernel<<<(B_*N_)/64, 256, smem1>>>(x, Wq, Wk, Wv);
    attn_kernel<<<NQB * B_ * NW_, 256, smem2>>>();
    mix_kernel<<<(B_*N_)/4, 256>>>(out);
}